// round 9
// baseline (speedup 1.0000x reference)
#include <cuda_runtime.h>

// Shape (N,C,T,V,M) = (256,3,600,25,2), f32.
// 1 unit = 20 rows = 500 float2. Sample = 90 units. Total 23040 units.
// 288 blocks x 80 units: perfect balance, single wave (288 <= 296 slots).
// Mainloop has COMPILE-TIME bounds; sample split handled by predicated adds.
#define NB       256
#define VV       25
#define TT       600
#define THREADS  500
#define UPB      80
#define BLOCKS   288
#define NTOT     23040000.0f

__device__ float        gA[BLOCKS][2][VV];
__device__ float        gS[BLOCKS][2][VV];
__device__ unsigned int g_count;   // zero at load; finalizer rearms each replay

__global__ __launch_bounds__(THREADS, 2)
void loss_balanced(const float2* __restrict__ x, const float2* __restrict__ y,
                   float* __restrict__ out)
{
    const int b   = blockIdx.x;
    const int tid = threadIdx.x;
    const int v   = tid % VV;
    const int r0  = tid / VV;                  // row offset within a unit (0..19)

    const int u0     = b * UPB;                // first global unit of this block
    const int offset = u0 % 90;
    int split = 90 - offset;                   // units belonging to first sample
    if (split > UPB) split = UPB;

    const float2* __restrict__ xp = x + (size_t)500 * u0;
    const float2* __restrict__ yp = y + (size_t)500 * u0;

    __shared__ float sA[2][VV];
    __shared__ float sS[2][VV];
    __shared__ bool  sFinal;
    if (tid < 2 * VV) { sA[tid / VV][tid % VV] = 0.0f; sS[tid / VV][tid % VV] = 0.0f; }
    if (tid == 0) sFinal = false;
    __syncthreads();

    // t at unit j is (20*u0 + r0 + 20*j) mod 600 -> incremental update
    int t = (1600 * b + r0) % 600;

    float a0A = 0.0f, a0S = 0.0f;              // first sample
    float a1A = 0.0f, a1S = 0.0f;              // second sample (if any)

    #pragma unroll 5
    for (int j = 0; j < UPB; ++j) {            // compile-time bounds -> full MLP
        const int idx = tid + j * THREADS;
        const float2 a  = __ldg(&xp[idx]);
        const float2 yv = __ldcs(&yp[idx]);    // read-once stream: evict-first

        const bool interior = (t != TT - 1);   // temporal diff guard + edge OOB guard
        float2 bn = make_float2(0.0f, 0.0f);
        if (interior) bn = __ldg(&xp[idx + VV]);

        const float dx = a.x - yv.x;
        const float dy = a.y - yv.y;
        float sq = dx * dx;
        sq = fmaf(dy, dy, sq);
        const float ab = interior ? (fabsf(bn.x - a.x) + fabsf(bn.y - a.y)) : 0.0f;

        if (j < split) {                       // runtime predicate, NOT a loop bound
            a0S += sq;  a0A += ab;
        } else {
            a1S += sq;  a1A += ab;
        }

        t += 20; if (t >= TT) t -= TT;
    }

    atomicAdd(&sA[0][v], a0A);  atomicAdd(&sS[0][v], a0S);
    atomicAdd(&sA[1][v], a1A);  atomicAdd(&sS[1][v], a1S);
    __syncthreads();

    if (tid < 2 * VV) {                        // deterministic plain stores
        const int s = tid / VV, vv = tid % VV;
        gA[b][s][vv] = sA[s][vv];
        gS[b][s][vv] = sS[s][vv];
    }
    __syncthreads();
    if (tid == 0) {
        __threadfence();
        unsigned int prev = atomicAdd(&g_count, 1u);
        sFinal = (prev == BLOCKS - 1);
    }
    __syncthreads();
    if (!sFinal) return;

    // ---- Finalizer (last-arriving block); fixed-order -> deterministic ----
    __threadfence();
    __shared__ float red[8];
    float part = 0.0f;
    if (tid < NB) {
        const int n   = tid;
        const int blo = (90 * n) / UPB;
        const int bhi = (90 * n + 89) / UPB;
        float tot = 0.0f, contrib = 0.0f;
        for (int vv = 0; vv < VV; ++vv) {
            float av = 0.0f, sv = 0.0f;
            for (int bb = blo; bb <= bhi; ++bb) {
                const int n0b  = (UPB * bb) / 90;
                const int slot = (n == n0b) ? 0 : 1;
                av += __ldcg(&gA[bb][slot][vv]);
                sv += __ldcg(&gS[bb][slot][vv]);
            }
            tot     += av;
            contrib += av * sv;
        }
        part = (float)VV * contrib / tot;

        #pragma unroll
        for (int o = 16; o > 0; o >>= 1)
            part += __shfl_xor_sync(0xffffffffu, part, o);
        if ((tid & 31) == 0) red[tid >> 5] = part;
    }
    __syncthreads();
    if (tid < 32) {
        float w = (tid < 8) ? red[tid] : 0.0f;
        #pragma unroll
        for (int o = 4; o > 0; o >>= 1)
            w += __shfl_xor_sync(0xffffffffu, w, o);
        if (tid == 0) {
            out[0]  = w / NTOT;
            g_count = 0u;                      // rearm for next graph replay
            __threadfence();
        }
    }
}

extern "C" void kernel_launch(void* const* d_in, const int* in_sizes, int n_in,
                              void* d_out, int out_size)
{
    (void)in_sizes; (void)n_in; (void)out_size;
    loss_balanced<<<BLOCKS, THREADS>>>((const float2*)d_in[0],
                                       (const float2*)d_in[1],
                                       (float*)d_out);
}

// round 10
// speedup vs baseline: 1.3942x; 1.3942x over previous
#include <cuda_runtime.h>

// Shape (N,C,T,V,M) = (256,3,600,25,2), f32
#define NB      256
#define TT      600
#define VV      25
#define ROWS    1800               // C*T rows of 50 floats per sample
#define F2_N    (ROWS * VV)        // 45000 float2 per sample
#define THREADS 500                // multiple of 25 -> fixed joint per thread
#define ROWS_IT (THREADS / VV)     // 20 rows per iteration
#define ITERS   (ROWS / ROWS_IT)   // 90 iterations
#define NTOT    23040000.0f

__device__ float        g_partial[NB];
__device__ unsigned int g_count;   // zero at load; finalizer rearms each replay

__global__ __launch_bounds__(THREADS, 2)
void loss_fused(const float2* __restrict__ x, const float2* __restrict__ y,
                float* __restrict__ out)
{
    const int n   = blockIdx.x;
    const int tid = threadIdx.x;
    const int v   = tid % VV;
    const int r0  = tid / VV;

    const float2* __restrict__ xn = x + (size_t)n * F2_N;
    const float2* __restrict__ yn = y + (size_t)n * F2_N;

    __shared__ float sAbs[VV];
    __shared__ float sSq[VV];
    __shared__ bool  sLast;
    if (tid < VV) { sAbs[tid] = 0.0f; sSq[tid] = 0.0f; }
    __syncthreads();

    float accA = 0.0f;   // sum |x[t+1]-x[t]|
    float accS = 0.0f;   // sum (x-y)^2

    // t == 599 (channel-edge row) happens iff r0==19 and j in {29,59,89}.
    // Instead of predicating the load, clamp its address: then b==a on those
    // instances, the |diff| contribution is exactly 0, and no guard is needed.
    // All loads unconditional -> maximal front-batching. Always in-bounds.
    const bool r19 = (r0 == ROWS_IT - 1);

    #pragma unroll 6
    for (int j = 0; j < ITERS; ++j) {
        const int idx  = tid + j * THREADS;
        const bool skip = r19 && (j == 29 || j == 59 || j == 89);
        const int nidx = idx + (skip ? 0 : VV);

        const float2 a  = __ldg(&xn[idx]);
        const float2 yv = __ldcs(&yn[idx]);    // read-once stream: evict-first
        const float2 b  = __ldg(&xn[nidx]);    // unconditional neighbor load

        const float dx = a.x - yv.x;
        const float dy = a.y - yv.y;
        accS = fmaf(dx, dx, accS);
        accS = fmaf(dy, dy, accS);

        accA += fabsf(b.x - a.x) + fabsf(b.y - a.y);   // 0 when skip (b==a)
    }

    atomicAdd(&sAbs[v], accA);   // 20 threads per joint slot; tail-time only
    atomicAdd(&sSq[v],  accS);
    __syncthreads();

    // Warp 0: per-sample combine, publish partial, elect last block
    if (tid < 32) {
        float myAbs = (tid < VV) ? sAbs[tid] : 0.0f;
        float mySq  = (tid < VV) ? sSq[tid]  : 0.0f;

        float tot = myAbs;
        #pragma unroll
        for (int o = 16; o > 0; o >>= 1)
            tot += __shfl_xor_sync(0xffffffffu, tot, o);

        float contrib = myAbs * mySq;
        #pragma unroll
        for (int o = 16; o > 0; o >>= 1)
            contrib += __shfl_xor_sync(0xffffffffu, contrib, o);

        if (tid == 0) {
            g_partial[n] = (float)VV * contrib / tot;
            __threadfence();
            unsigned int prev = atomicAdd(&g_count, 1u);
            sLast = (prev == NB - 1);
        }
    }
    __syncthreads();

    // Last-arriving block: reduce all 256 partials (fixed order -> deterministic)
    if (sLast && tid < 32) {
        __threadfence();
        float val = 0.0f;
        #pragma unroll
        for (int k = 0; k < NB / 32; ++k)
            val += __ldcg(&g_partial[tid + k * 32]);
        #pragma unroll
        for (int o = 16; o > 0; o >>= 1)
            val += __shfl_xor_sync(0xffffffffu, val, o);
        if (tid == 0) {
            out[0]  = val / NTOT;
            g_count = 0u;            // rearm for next graph replay
            __threadfence();
        }
    }
}

extern "C" void kernel_launch(void* const* d_in, const int* in_sizes, int n_in,
                              void* d_out, int out_size)
{
    (void)in_sizes; (void)n_in; (void)out_size;
    loss_fused<<<NB, THREADS>>>((const float2*)d_in[0],
                                (const float2*)d_in[1],
                                (float*)d_out);
}